// round 1
// baseline (speedup 1.0000x reference)
#include <cuda_runtime.h>

#define NN 100000
#define NE 1600000
#define C  64

// ---------------- device scratch (no allocs allowed) ----------------
__device__ float g_e[(size_t)NE * C];     // edge features, CSR-sorted order (410MB)
__device__ float g_hA[NN * C];
__device__ float g_hB[NN * C];
__device__ float g_z[NN * C];
__device__ int   g_src[NE];               // src node per CSR position
__device__ int   g_eid[NE];               // original edge id per CSR position
__device__ int   g_offs[NN + 1];
__device__ int   g_deg[NN];
__device__ int   g_cur[NN];
__device__ int   g_bsum[128];

// ---------------- CSR build ----------------
__global__ void k_clear() {
    int i = blockIdx.x * blockDim.x + threadIdx.x;
    if (i < NN) { g_deg[i] = 0; g_cur[i] = 0; }
}

__global__ void k_hist(const int* __restrict__ ei) {
    int i = blockIdx.x * blockDim.x + threadIdx.x;
    if (i < NE) atomicAdd(&g_deg[ei[NE + i]], 1);
}

__global__ void k_scan1() {
    int t = threadIdx.x;
    int idx = blockIdx.x * 1024 + t;
    int v = (idx < NN) ? g_deg[idx] : 0;
    int x = v;
    int lane = t & 31, w = t >> 5;
    #pragma unroll
    for (int o = 1; o < 32; o <<= 1) {
        int y = __shfl_up_sync(0xffffffffu, x, o);
        if (lane >= o) x += y;
    }
    __shared__ int ws[32];
    if (lane == 31) ws[w] = x;
    __syncthreads();
    if (w == 0) {
        int y = ws[lane];
        #pragma unroll
        for (int o = 1; o < 32; o <<= 1) {
            int z2 = __shfl_up_sync(0xffffffffu, y, o);
            if (lane >= o) y += z2;
        }
        ws[lane] = y;
    }
    __syncthreads();
    int incl = x + (w > 0 ? ws[w - 1] : 0);
    if (idx < NN) g_offs[idx] = incl - v;   // exclusive prefix
    if (t == 1023) g_bsum[blockIdx.x] = incl;
}

__global__ void k_scan2(int nb) {
    if (blockIdx.x == 0 && threadIdx.x == 0) {
        int run = 0;
        for (int i = 0; i < nb; i++) { int tmp = g_bsum[i]; g_bsum[i] = run; run += tmp; }
    }
}

__global__ void k_scan3() {
    int idx = blockIdx.x * blockDim.x + threadIdx.x;
    if (idx < NN) g_offs[idx] += g_bsum[idx >> 10];
    if (idx == 0) g_offs[NN] = NE;
}

__global__ void k_scatter(const int* __restrict__ ei) {
    int i = blockIdx.x * blockDim.x + threadIdx.x;
    if (i < NE) {
        int d = ei[NE + i];
        int p = g_offs[d] + atomicAdd(&g_cur[d], 1);
        g_src[p] = ei[i];
        g_eid[p] = i;
    }
}

// ---------------- 64x64 GEMM: out[r] = A[gather?gather[r]:r] @ W + b ----------------
// Block: 256 threads, 64 rows. Thread computes 4 rows x 4 cols.
__global__ __launch_bounds__(256) void k_gemm64(
    const float* __restrict__ A, const int* __restrict__ gather,
    const float* __restrict__ W, const float* __restrict__ bias,
    float* __restrict__ out, int nrows)
{
    __shared__ float At[64][68];   // At[k][r] = A[base+r][k], padded
    __shared__ float Ws[64][64];
    int t = threadIdx.x;
    for (int i = t; i < 4096; i += 256) Ws[i >> 6][i & 63] = W[i];

    int base = blockIdx.x * 64;
    {
        int r = t >> 2, q = t & 3;
        int row = base + r;
        if (row < nrows) {
            size_t arow = gather ? (size_t)__ldg(&gather[row]) : (size_t)row;
            const float* src = A + arow * 64;
            #pragma unroll
            for (int j = 0; j < 4; j++) {
                int k = q * 4 + j * 16;               // coalesced 64B per row per step
                float4 v = *(const float4*)(src + k);
                At[k + 0][r] = v.x; At[k + 1][r] = v.y;
                At[k + 2][r] = v.z; At[k + 3][r] = v.w;
            }
        } else {
            #pragma unroll
            for (int j = 0; j < 4; j++) {
                int k = q * 4 + j * 16;
                At[k + 0][r] = 0.f; At[k + 1][r] = 0.f;
                At[k + 2][r] = 0.f; At[k + 3][r] = 0.f;
            }
        }
    }
    __syncthreads();

    int cq = t & 15, rq = t >> 4;
    float acc[4][4];
    #pragma unroll
    for (int r = 0; r < 4; r++)
        #pragma unroll
        for (int c = 0; c < 4; c++) acc[r][c] = __ldg(&bias[cq * 4 + c]);

    #pragma unroll 8
    for (int k = 0; k < 64; k++) {
        float4 a4 = *(const float4*)&At[k][rq * 4];
        float4 w4 = *(const float4*)&Ws[k][cq * 4];
        float a[4] = {a4.x, a4.y, a4.z, a4.w};
        float wv[4] = {w4.x, w4.y, w4.z, w4.w};
        #pragma unroll
        for (int r = 0; r < 4; r++)
            #pragma unroll
            for (int c = 0; c < 4; c++)
                acc[r][c] = fmaf(a[r], wv[c], acc[r][c]);
    }

    #pragma unroll
    for (int r = 0; r < 4; r++) {
        int row = base + rq * 4 + r;
        if (row < nrows)
            *(float4*)(out + (size_t)row * 64 + cq * 4) =
                make_float4(acc[r][0], acc[r][1], acc[r][2], acc[r][3]);
    }
}

// ---------------- LayerNorm + ReLU (warp per node) ----------------
__global__ __launch_bounds__(256) void k_ln_relu(
    const float* __restrict__ in, const float* __restrict__ gamma,
    const float* __restrict__ beta, float* __restrict__ out)
{
    int t = threadIdx.x;
    int node = blockIdx.x * 8 + (t >> 5);
    int l = t & 31;
    if (node >= NN) return;
    float2 v = ((const float2*)in)[(size_t)node * 32 + l];
    float s = v.x + v.y;
    #pragma unroll
    for (int o = 16; o > 0; o >>= 1) s += __shfl_xor_sync(0xffffffffu, s, o);
    float mu = s * (1.0f / 64.0f);
    float dx = v.x - mu, dy = v.y - mu;
    float q = dx * dx + dy * dy;
    #pragma unroll
    for (int o = 16; o > 0; o >>= 1) q += __shfl_xor_sync(0xffffffffu, q, o);
    float rs = rsqrtf(q * (1.0f / 64.0f) + 1e-5f);
    float2 g = ((const float2*)gamma)[l];
    float2 b = ((const float2*)beta)[l];
    float2 o2;
    o2.x = fmaxf(fmaf(dx * rs, g.x, b.x), 0.f);
    o2.y = fmaxf(fmaf(dy * rs, g.y, b.y), 0.f);
    ((float2*)out)[(size_t)node * 32 + l] = o2;
}

// ---------------- GENConv: softmax-aggregate + (aggr+z)@W + b [+ residual] ----------------
// Warp per destination node; e read in CSR order (coalesced), z gathered from L2.
template<bool RES>
__global__ __launch_bounds__(256) void k_agg_conv(
    const float* __restrict__ z, const float* __restrict__ hres,
    const float* __restrict__ W, const float* __restrict__ bias,
    const float* __restrict__ tptr, float* __restrict__ hout)
{
    __shared__ float Wsm[4096];
    int t = threadIdx.x;
    for (int i = t; i < 4096; i += 256) Wsm[i] = W[i];
    __syncthreads();

    int node = blockIdx.x * 8 + (t >> 5);
    int l = t & 31;
    if (node >= NN) return;

    float tv = __ldg(tptr);
    int beg = g_offs[node], end = g_offs[node + 1];
    const float2* e2 = (const float2*)g_e;
    const float2* z2 = (const float2*)z;

    float d0 = 0.f, d1 = 0.f, s0 = 0.f, s1 = 0.f;
    #pragma unroll 2
    for (int p = beg; p < end; p++) {
        int sidx = __ldg(&g_src[p]);
        float2 ev = e2[(size_t)p * 32 + l];
        float2 zv = z2[(size_t)sidx * 32 + l];
        float m0 = fmaxf(ev.x + zv.x, 0.f) + 1e-7f;
        float m1 = fmaxf(ev.y + zv.y, 0.f) + 1e-7f;
        float x0 = __expf(m0 * tv);
        float x1 = __expf(m1 * tv);
        d0 += x0; d1 += x1;
        s0 = fmaf(x0, m0, s0); s1 = fmaf(x1, m1, s1);
    }

    float2 zn = z2[(size_t)node * 32 + l];
    float u0 = __fdividef(s0, d0 + 1e-16f) + zn.x;
    float u1 = __fdividef(s1, d1 + 1e-16f) + zn.y;

    float acc0 = __ldg(&bias[2 * l]);
    float acc1 = __ldg(&bias[2 * l + 1]);
    const float2* W2 = (const float2*)Wsm;
    #pragma unroll
    for (int k = 0; k < 64; k += 2) {
        float uk0 = __shfl_sync(0xffffffffu, u0, k >> 1);
        float uk1 = __shfl_sync(0xffffffffu, u1, k >> 1);
        float2 w0 = W2[k * 32 + l];
        float2 w1 = W2[(k + 1) * 32 + l];
        acc0 = fmaf(uk0, w0.x, acc0);
        acc1 = fmaf(uk0, w0.y, acc1);
        acc0 = fmaf(uk1, w1.x, acc0);
        acc1 = fmaf(uk1, w1.y, acc1);
    }
    if (RES) {
        float2 hv = ((const float2*)hres)[(size_t)node * 32 + l];
        acc0 += hv.x; acc1 += hv.y;
    }
    ((float2*)hout)[(size_t)node * 32 + l] = make_float2(acc0, acc1);
}

// ---------------- launch ----------------
extern "C" void kernel_launch(void* const* d_in, const int* in_sizes, int n_in,
                              void* d_out, int out_size)
{
    const float* x         = (const float*)d_in[0];
    const float* edge_attr = (const float*)d_in[1];
    const int*   ei        = (const int*)d_in[2];
    const float* W_ne      = (const float*)d_in[3];
    const float* b_ne      = (const float*)d_in[4];
    const float* W_ee      = (const float*)d_in[5];
    const float* b_ee      = (const float*)d_in[6];
    const float* W_conv    = (const float*)d_in[7];
    const float* b_conv    = (const float*)d_in[8];
    const float* tarr      = (const float*)d_in[9];
    const float* gamma     = (const float*)d_in[10];
    const float* beta      = (const float*)d_in[11];
    const float* W_lin     = (const float*)d_in[12];
    const float* b_lin     = (const float*)d_in[13];
    float* out = (float*)d_out;

    float *p_e, *p_hA, *p_hB, *p_z;
    int   *p_eid;
    cudaGetSymbolAddress((void**)&p_e,   g_e);
    cudaGetSymbolAddress((void**)&p_hA,  g_hA);
    cudaGetSymbolAddress((void**)&p_hB,  g_hB);
    cudaGetSymbolAddress((void**)&p_z,   g_z);
    cudaGetSymbolAddress((void**)&p_eid, g_eid);

    const int NB_N  = (NN + 255) / 256;     // 391
    const int NB_E  = (NE + 255) / 256;     // 6250
    const int NB_W  = (NN + 7) / 8;         // 12500 (warp-per-node kernels)
    const int NB_G  = (NN + 63) / 64;       // 1563
    const int NB_GE = NE / 64;              // 25000
    const int NB_S  = (NN + 1023) / 1024;   // 98

    // CSR build (every call; same inputs -> same work)
    k_clear  <<<NB_N, 256>>>();
    k_hist   <<<NB_E, 256>>>(ei);
    k_scan1  <<<NB_S, 1024>>>();
    k_scan2  <<<1, 32>>>(NB_S);
    k_scan3  <<<NB_N, 256>>>();
    k_scatter<<<NB_E, 256>>>(ei);

    // encoders
    k_gemm64<<<NB_G,  256>>>(x,         nullptr, W_ne, b_ne, p_hA, NN);
    k_gemm64<<<NB_GE, 256>>>(edge_attr, p_eid,   W_ee, b_ee, p_e,  NE);

    // layer 0: conv on h directly, no residual: hA -> hB
    k_agg_conv<false><<<NB_W, 256>>>(p_hA, nullptr, W_conv, b_conv, tarr, p_hB);
    // layer 1: hB -> hA
    k_ln_relu<<<NB_W, 256>>>(p_hB, gamma + 64,  beta + 64,  p_z);
    k_agg_conv<true><<<NB_W, 256>>>(p_z, p_hB, W_conv + 4096,  b_conv + 64,  tarr + 1, p_hA);
    // layer 2: hA -> hB
    k_ln_relu<<<NB_W, 256>>>(p_hA, gamma + 128, beta + 128, p_z);
    k_agg_conv<true><<<NB_W, 256>>>(p_z, p_hA, W_conv + 8192,  b_conv + 128, tarr + 2, p_hB);
    // layer 3: hB -> hA
    k_ln_relu<<<NB_W, 256>>>(p_hB, gamma + 192, beta + 192, p_z);
    k_agg_conv<true><<<NB_W, 256>>>(p_z, p_hB, W_conv + 12288, b_conv + 192, tarr + 3, p_hA);

    // final: LN(gamma0,beta0) -> relu -> @W_lin + b_lin
    k_ln_relu<<<NB_W, 256>>>(p_hA, gamma, beta, p_z);
    k_gemm64<<<NB_G, 256>>>(p_z, nullptr, W_lin, b_lin, out, NN);
}

// round 3
// speedup vs baseline: 1.1273x; 1.1273x over previous
#include <cuda_runtime.h>
#include <cuda_fp16.h>
#include <cuda_bf16.h>
#include <cstdint>

#define NN 100000
#define NE 1600000

// ---------------- device scratch (no allocs allowed) ----------------
__device__ __half g_eh[(size_t)NE * 64];   // edge features fp16, CSR order (205MB)
__device__ __half g_zh[(size_t)NN * 64];   // LN/encoder output, fp16 (gather source)
__device__ float  g_hA[NN * 64];
__device__ float  g_hB[NN * 64];
__device__ float  g_zf[NN * 64];           // final LN output fp32
__device__ int    g_src[NE];
__device__ int    g_eid[NE];
__device__ int    g_offs[NN + 1];
__device__ int    g_deg[NN];
__device__ int    g_cur[NN];
__device__ int    g_bsum[128];

// ---------------- CSR build ----------------
__global__ void k_clear() {
    int i = blockIdx.x * blockDim.x + threadIdx.x;
    if (i < NN) { g_deg[i] = 0; g_cur[i] = 0; }
}
__global__ void k_hist(const int* __restrict__ ei) {
    int i = blockIdx.x * blockDim.x + threadIdx.x;
    if (i < NE) atomicAdd(&g_deg[ei[NE + i]], 1);
}
__global__ void k_scan1() {
    int t = threadIdx.x;
    int idx = blockIdx.x * 1024 + t;
    int v = (idx < NN) ? g_deg[idx] : 0;
    int x = v;
    int lane = t & 31, w = t >> 5;
    #pragma unroll
    for (int o = 1; o < 32; o <<= 1) {
        int y = __shfl_up_sync(0xffffffffu, x, o);
        if (lane >= o) x += y;
    }
    __shared__ int ws[32];
    if (lane == 31) ws[w] = x;
    __syncthreads();
    if (w == 0) {
        int y = ws[lane];
        #pragma unroll
        for (int o = 1; o < 32; o <<= 1) {
            int z2 = __shfl_up_sync(0xffffffffu, y, o);
            if (lane >= o) y += z2;
        }
        ws[lane] = y;
    }
    __syncthreads();
    int incl = x + (w > 0 ? ws[w - 1] : 0);
    if (idx < NN) g_offs[idx] = incl - v;
    if (t == 1023) g_bsum[blockIdx.x] = incl;
}
__global__ void k_scan2(int nb) {
    if (threadIdx.x == 0) {
        int run = 0;
        for (int i = 0; i < nb; i++) { int tmp = g_bsum[i]; g_bsum[i] = run; run += tmp; }
    }
}
__global__ void k_scan3() {
    int idx = blockIdx.x * blockDim.x + threadIdx.x;
    if (idx < NN) g_offs[idx] += g_bsum[idx >> 10];
    if (idx == 0) g_offs[NN] = NE;
}
__global__ void k_scatter(const int* __restrict__ ei) {
    int i = blockIdx.x * blockDim.x + threadIdx.x;
    if (i < NE) {
        int d = ei[NE + i];
        int p = g_offs[d] + atomicAdd(&g_cur[d], 1);
        g_src[p] = ei[i];
        g_eid[p] = i;
    }
}

// ---------------- tensor-core GEMM: out[r] = A[gather?g[r]:r] @ W + b ----------------
// bf16 hi/lo 3-pass split (near-fp32 accuracy). Block = 256 thr, 64 rows x 64 cols.
// OUT_MODE: 0 = fp32; 1 = fp16; 2 = fp32 + fp16 copy.
#define LDSM4(R0,R1,R2,R3,ADDR) \
    asm volatile("ldmatrix.sync.aligned.m8n8.x4.shared.b16 {%0,%1,%2,%3}, [%4];" \
        : "=r"(R0),"=r"(R1),"=r"(R2),"=r"(R3) : "r"(ADDR))
#define MMA_BF16(C0,C1,C2,C3,A0,A1,A2,A3,B0,B1) \
    asm volatile("mma.sync.aligned.m16n8k16.row.col.f32.bf16.bf16.f32 " \
        "{%0,%1,%2,%3},{%4,%5,%6,%7},{%8,%9},{%0,%1,%2,%3};" \
        : "+f"(C0),"+f"(C1),"+f"(C2),"+f"(C3) \
        : "r"(A0),"r"(A1),"r"(A2),"r"(A3),"r"(B0),"r"(B1))

__device__ __forceinline__ uint32_t sm_addr(const void* p) {
    return (uint32_t)__cvta_generic_to_shared(p);
}

template<int OUT_MODE>
__global__ __launch_bounds__(256) void k_gemm_tc(
    const float* __restrict__ A, const int* __restrict__ gather,
    const float* __restrict__ W, const float* __restrict__ bias,
    float* __restrict__ outF, __half* __restrict__ outH, int nrows)
{
    __shared__ __align__(16) __nv_bfloat16 Ah[64][72];
    __shared__ __align__(16) __nv_bfloat16 Al[64][72];
    __shared__ __align__(16) __nv_bfloat16 Bh[64][72];   // W^T: [n][k]
    __shared__ __align__(16) __nv_bfloat16 Bl[64][72];

    int t = threadIdx.x;
    for (int i = t; i < 4096; i += 256) {
        int k = i >> 6, n = i & 63;
        float w = W[i];
        __nv_bfloat16 h = __float2bfloat16(w);
        Bh[n][k] = h;
        Bl[n][k] = __float2bfloat16(w - __bfloat162float(h));
    }

    int base = blockIdx.x * 64;
    {
        int r = t >> 2, q = t & 3;
        int row = base + r;
        const float* src = nullptr;
        if (row < nrows) {
            long arow = gather ? (long)__ldg(&gather[row]) : (long)row;
            src = A + arow * 64;
        }
        #pragma unroll
        for (int j = 0; j < 4; j++) {
            int k = q * 16 + j * 4;
            float4 v = src ? *(const float4*)(src + k) : make_float4(0.f,0.f,0.f,0.f);
            __nv_bfloat16 h0 = __float2bfloat16(v.x);
            __nv_bfloat16 h1 = __float2bfloat16(v.y);
            __nv_bfloat16 h2 = __float2bfloat16(v.z);
            __nv_bfloat16 h3 = __float2bfloat16(v.w);
            *(__nv_bfloat162*)&Ah[r][k]   = __nv_bfloat162(h0, h1);
            *(__nv_bfloat162*)&Ah[r][k+2] = __nv_bfloat162(h2, h3);
            __nv_bfloat16 l0 = __float2bfloat16(v.x - __bfloat162float(h0));
            __nv_bfloat16 l1 = __float2bfloat16(v.y - __bfloat162float(h1));
            __nv_bfloat16 l2 = __float2bfloat16(v.z - __bfloat162float(h2));
            __nv_bfloat16 l3 = __float2bfloat16(v.w - __bfloat162float(h3));
            *(__nv_bfloat162*)&Al[r][k]   = __nv_bfloat162(l0, l1);
            *(__nv_bfloat162*)&Al[r][k+2] = __nv_bfloat162(l2, l3);
        }
    }
    __syncthreads();

    int w = t >> 5, lane = t & 31;
    int row_base = (w & 3) * 16;
    int col_base = (w >> 2) * 32;
    int tr = lane & 7, sel = lane >> 3;

    float acc[4][4];
    #pragma unroll
    for (int nt = 0; nt < 4; nt++) {
        int col = col_base + nt * 8 + (lane & 3) * 2;
        float b0 = __ldg(&bias[col]), b1 = __ldg(&bias[col + 1]);
        acc[nt][0] = b0; acc[nt][1] = b1; acc[nt][2] = b0; acc[nt][3] = b1;
    }

    int ar = row_base + tr + ((sel & 1) << 3);
    #pragma unroll
    for (int kstep = 0; kstep < 4; kstep++) {
        int kb = kstep * 16;
        int ak = kb + ((sel >> 1) << 3);
        uint32_t ah0, ah1, ah2, ah3, al0, al1, al2, al3;
        LDSM4(ah0, ah1, ah2, ah3, sm_addr(&Ah[ar][ak]));
        LDSM4(al0, al1, al2, al3, sm_addr(&Al[ar][ak]));

        #pragma unroll
        for (int hnt = 0; hnt < 2; hnt++) {
            int nb = col_base + hnt * 16;
            int bn = nb + tr + ((sel & 2) << 2);   // +8 for sel 2,3
            int bk = kb + ((sel & 1) << 3);        // +8 for sel 1,3
            uint32_t bh0, bh1, bh2, bh3, bl0, bl1, bl2, bl3;
            LDSM4(bh0, bh1, bh2, bh3, sm_addr(&Bh[bn][bk]));
            LDSM4(bl0, bl1, bl2, bl3, sm_addr(&Bl[bn][bk]));
            int n0 = hnt * 2, n1 = hnt * 2 + 1;
            MMA_BF16(acc[n0][0],acc[n0][1],acc[n0][2],acc[n0][3], ah0,ah1,ah2,ah3, bh0,bh1);
            MMA_BF16(acc[n0][0],acc[n0][1],acc[n0][2],acc[n0][3], ah0,ah1,ah2,ah3, bl0,bl1);
            MMA_BF16(acc[n0][0],acc[n0][1],acc[n0][2],acc[n0][3], al0,al1,al2,al3, bh0,bh1);
            MMA_BF16(acc[n1][0],acc[n1][1],acc[n1][2],acc[n1][3], ah0,ah1,ah2,ah3, bh2,bh3);
            MMA_BF16(acc[n1][0],acc[n1][1],acc[n1][2],acc[n1][3], ah0,ah1,ah2,ah3, bl2,bl3);
            MMA_BF16(acc[n1][0],acc[n1][1],acc[n1][2],acc[n1][3], al0,al1,al2,al3, bh2,bh3);
        }
    }

    #pragma unroll
    for (int nt = 0; nt < 4; nt++) {
        int col = col_base + nt * 8 + (lane & 3) * 2;
        int r0 = base + row_base + (lane >> 2);
        int r1 = r0 + 8;
        if (r0 < nrows) {
            if (OUT_MODE != 1)
                *(float2*)(outF + (size_t)r0 * 64 + col) = make_float2(acc[nt][0], acc[nt][1]);
            if (OUT_MODE != 0)
                *(__half2*)(outH + (size_t)r0 * 64 + col) = __floats2half2_rn(acc[nt][0], acc[nt][1]);
        }
        if (r1 < nrows) {
            if (OUT_MODE != 1)
                *(float2*)(outF + (size_t)r1 * 64 + col) = make_float2(acc[nt][2], acc[nt][3]);
            if (OUT_MODE != 0)
                *(__half2*)(outH + (size_t)r1 * 64 + col) = __floats2half2_rn(acc[nt][2], acc[nt][3]);
        }
    }
}

// ---------------- LayerNorm + ReLU (warp per node) ----------------
template<bool HALF_OUT>
__global__ __launch_bounds__(256) void k_ln_relu(
    const float* __restrict__ in, const float* __restrict__ gamma,
    const float* __restrict__ beta, float* __restrict__ outF, __half* __restrict__ outH)
{
    int t = threadIdx.x;
    int node = blockIdx.x * 8 + (t >> 5);
    int l = t & 31;
    if (node >= NN) return;
    float2 v = ((const float2*)in)[(size_t)node * 32 + l];
    float s = v.x + v.y;
    #pragma unroll
    for (int o = 16; o > 0; o >>= 1) s += __shfl_xor_sync(0xffffffffu, s, o);
    float mu = s * (1.0f / 64.0f);
    float dx = v.x - mu, dy = v.y - mu;
    float q = dx * dx + dy * dy;
    #pragma unroll
    for (int o = 16; o > 0; o >>= 1) q += __shfl_xor_sync(0xffffffffu, q, o);
    float rs = rsqrtf(q * (1.0f / 64.0f) + 1e-5f);
    float2 g = ((const float2*)gamma)[l];
    float2 b = ((const float2*)beta)[l];
    float ox = fmaxf(fmaf(dx * rs, g.x, b.x), 0.f);
    float oy = fmaxf(fmaf(dy * rs, g.y, b.y), 0.f);
    if (HALF_OUT)
        ((__half2*)outH)[(size_t)node * 32 + l] = __floats2half2_rn(ox, oy);
    else
        ((float2*)outF)[(size_t)node * 32 + l] = make_float2(ox, oy);
}

// ---------------- GENConv: softmax-aggregate + (aggr+z)@W + b [+ residual] ----------------
template<bool RES>
__global__ __launch_bounds__(256) void k_agg_conv(
    const __half* __restrict__ z, const float* __restrict__ hres,
    const float* __restrict__ W, const float* __restrict__ bias,
    const float* __restrict__ tptr, float* __restrict__ hout)
{
    __shared__ float Wsm[4096];
    int t = threadIdx.x;
    for (int i = t; i < 4096; i += 256) Wsm[i] = W[i];
    __syncthreads();

    int node = blockIdx.x * 8 + (t >> 5);
    int l = t & 31;
    if (node >= NN) return;

    float tv = __ldg(tptr);
    int beg = g_offs[node], end = g_offs[node + 1];
    const __half2* e2 = (const __half2*)g_eh;
    const __half2* z2 = (const __half2*)z;

    float d0 = 0.f, d1 = 0.f, s0 = 0.f, s1 = 0.f;
    #pragma unroll 2
    for (int p = beg; p < end; p++) {
        int sidx = __ldg(&g_src[p]);
        float2 ev = __half22float2(e2[(size_t)p * 32 + l]);
        float2 zv = __half22float2(__ldg(&z2[(size_t)sidx * 32 + l]));
        float m0 = fmaxf(ev.x + zv.x, 0.f) + 1e-7f;
        float m1 = fmaxf(ev.y + zv.y, 0.f) + 1e-7f;
        float x0 = __expf(m0 * tv);
        float x1 = __expf(m1 * tv);
        d0 += x0; d1 += x1;
        s0 = fmaf(x0, m0, s0); s1 = fmaf(x1, m1, s1);
    }

    float2 zn = __half22float2(z2[(size_t)node * 32 + l]);
    float u0 = __fdividef(s0, d0 + 1e-16f) + zn.x;
    float u1 = __fdividef(s1, d1 + 1e-16f) + zn.y;

    float acc0 = __ldg(&bias[2 * l]);
    float acc1 = __ldg(&bias[2 * l + 1]);
    const float2* W2 = (const float2*)Wsm;
    #pragma unroll
    for (int k = 0; k < 64; k += 2) {
        float uk0 = __shfl_sync(0xffffffffu, u0, k >> 1);
        float uk1 = __shfl_sync(0xffffffffu, u1, k >> 1);
        float2 w0 = W2[k * 32 + l];
        float2 w1 = W2[(k + 1) * 32 + l];
        acc0 = fmaf(uk0, w0.x, acc0);
        acc1 = fmaf(uk0, w0.y, acc1);
        acc0 = fmaf(uk1, w1.x, acc0);
        acc1 = fmaf(uk1, w1.y, acc1);
    }
    if (RES) {
        float2 hv = ((const float2*)hres)[(size_t)node * 32 + l];
        acc0 += hv.x; acc1 += hv.y;
    }
    ((float2*)hout)[(size_t)node * 32 + l] = make_float2(acc0, acc1);
}

// ---------------- launch ----------------
extern "C" void kernel_launch(void* const* d_in, const int* in_sizes, int n_in,
                              void* d_out, int out_size)
{
    const float* x         = (const float*)d_in[0];
    const float* edge_attr = (const float*)d_in[1];
    const int*   ei        = (const int*)d_in[2];
    const float* W_ne      = (const float*)d_in[3];
    const float* b_ne      = (const float*)d_in[4];
    const float* W_ee      = (const float*)d_in[5];
    const float* b_ee      = (const float*)d_in[6];
    const float* W_conv    = (const float*)d_in[7];
    const float* b_conv    = (const float*)d_in[8];
    const float* tarr      = (const float*)d_in[9];
    const float* gamma     = (const float*)d_in[10];
    const float* beta      = (const float*)d_in[11];
    const float* W_lin     = (const float*)d_in[12];
    const float* b_lin     = (const float*)d_in[13];
    float* out = (float*)d_out;

    float *p_hA, *p_hB, *p_zf;
    __half *p_eh, *p_zh;
    int *p_eid;
    cudaGetSymbolAddress((void**)&p_eh,  g_eh);
    cudaGetSymbolAddress((void**)&p_zh,  g_zh);
    cudaGetSymbolAddress((void**)&p_hA,  g_hA);
    cudaGetSymbolAddress((void**)&p_hB,  g_hB);
    cudaGetSymbolAddress((void**)&p_zf,  g_zf);
    cudaGetSymbolAddress((void**)&p_eid, g_eid);

    const int NB_N  = (NN + 255) / 256;
    const int NB_E  = (NE + 255) / 256;
    const int NB_W  = (NN + 7) / 8;
    const int NB_G  = (NN + 63) / 64;
    const int NB_GE = NE / 64;
    const int NB_S  = (NN + 1023) / 1024;

    // CSR build
    k_clear  <<<NB_N, 256>>>();
    k_hist   <<<NB_E, 256>>>(ei);
    k_scan1  <<<NB_S, 1024>>>();
    k_scan2  <<<1, 32>>>(NB_S);
    k_scan3  <<<NB_N, 256>>>();
    k_scatter<<<NB_E, 256>>>(ei);

    // encoders (tensor cores, bf16 split)
    k_gemm_tc<2><<<NB_G,  256>>>(x,         nullptr, W_ne, b_ne, p_hA, p_zh, NN);
    k_gemm_tc<1><<<NB_GE, 256>>>(edge_attr, p_eid,   W_ee, b_ee, nullptr, p_eh, NE);

    // layer 0: conv on h directly (z = fp16 copy of h), no residual: -> hB
    k_agg_conv<false><<<NB_W, 256>>>(p_zh, nullptr, W_conv, b_conv, tarr, p_hB);
    // layer 1
    k_ln_relu<true><<<NB_W, 256>>>(p_hB, gamma + 64,  beta + 64,  nullptr, p_zh);
    k_agg_conv<true><<<NB_W, 256>>>(p_zh, p_hB, W_conv + 4096,  b_conv + 64,  tarr + 1, p_hA);
    // layer 2
    k_ln_relu<true><<<NB_W, 256>>>(p_hA, gamma + 128, beta + 128, nullptr, p_zh);
    k_agg_conv<true><<<NB_W, 256>>>(p_zh, p_hA, W_conv + 8192,  b_conv + 128, tarr + 2, p_hB);
    // layer 3
    k_ln_relu<true><<<NB_W, 256>>>(p_hB, gamma + 192, beta + 192, nullptr, p_zh);
    k_agg_conv<true><<<NB_W, 256>>>(p_zh, p_hB, W_conv + 12288, b_conv + 192, tarr + 3, p_hA);

    // final: LN(gamma0,beta0) -> relu (fp32) -> @W_lin + b_lin
    k_ln_relu<false><<<NB_W, 256>>>(p_hA, gamma, beta, p_zf, nullptr);
    k_gemm_tc<0><<<NB_G, 256>>>(p_zf, nullptr, W_lin, b_lin, out, nullptr, NN);
}

// round 4
// speedup vs baseline: 1.3396x; 1.1884x over previous
#include <cuda_runtime.h>
#include <cuda_fp16.h>
#include <cuda_bf16.h>
#include <cstdint>

#define NN 100000
#define NE 1600000

// ---------------- device scratch (no allocs allowed) ----------------
__device__ __half g_eh[(size_t)NE * 64];    // edge features fp16, CSR order (205MB)
__device__ __half g_zh0[(size_t)NN * 64];   // z double buffers (fp16)
__device__ __half g_zh1[(size_t)NN * 64];
__device__ float  g_hA[NN * 64];
__device__ float  g_hB[NN * 64];
__device__ float  g_zf[NN * 64];            // final LN output fp32
__device__ int    g_src[NE];
__device__ int    g_eid[NE];
__device__ int    g_offs[NN + 1];
__device__ int    g_deg[NN];
__device__ int    g_cur[NN];
__device__ int    g_bsum[128];

// ---------------- CSR build ----------------
__global__ void k_hist(const int* __restrict__ ei) {
    int i = blockIdx.x * blockDim.x + threadIdx.x;
    if (i < NE) atomicAdd(&g_deg[ei[NE + i]], 1);
}
// block-level scan of deg -> offs (exclusive within block); also zeros deg for next call
__global__ void k_scan1() {
    int t = threadIdx.x;
    int idx = blockIdx.x * 1024 + t;
    int v = (idx < NN) ? g_deg[idx] : 0;
    if (idx < NN) g_deg[idx] = 0;          // ready for next replay's k_hist
    int x = v;
    int lane = t & 31, w = t >> 5;
    #pragma unroll
    for (int o = 1; o < 32; o <<= 1) {
        int y = __shfl_up_sync(0xffffffffu, x, o);
        if (lane >= o) x += y;
    }
    __shared__ int ws[32];
    if (lane == 31) ws[w] = x;
    __syncthreads();
    if (w == 0) {
        int y = ws[lane];
        #pragma unroll
        for (int o = 1; o < 32; o <<= 1) {
            int z2 = __shfl_up_sync(0xffffffffu, y, o);
            if (lane >= o) y += z2;
        }
        ws[lane] = y;
    }
    __syncthreads();
    int incl = x + (w > 0 ? ws[w - 1] : 0);
    if (idx < NN) g_offs[idx] = incl - v;
    if (t == 1023) g_bsum[blockIdx.x] = incl;
}
// fused: every block scans bsum (98 entries) in smem, then adds to its offs slice; zeros cur
__global__ __launch_bounds__(256) void k_scan23() {
    __shared__ int bs[128];
    __shared__ int ws[4];
    int t = threadIdx.x;
    const int nb = (NN + 1023) >> 10;
    int v = 0, x = 0;
    int lane = t & 31, w = t >> 5;
    if (t < 128) {
        v = (t < nb) ? g_bsum[t] : 0;
        x = v;
        #pragma unroll
        for (int o = 1; o < 32; o <<= 1) {
            int y = __shfl_up_sync(0xffffffffu, x, o);
            if (lane >= o) x += y;
        }
        if (lane == 31) ws[w] = x;
    }
    __syncthreads();
    if (t < 128) {
        int add = 0;
        if (w == 1) add = ws[0];
        else if (w == 2) add = ws[0] + ws[1];
        else if (w == 3) add = ws[0] + ws[1] + ws[2];
        bs[t] = x + add - v;   // exclusive prefix
    }
    __syncthreads();
    int idx = blockIdx.x * 256 + t;
    if (idx < NN) { g_offs[idx] += bs[idx >> 10]; g_cur[idx] = 0; }
    if (idx == 0) g_offs[NN] = NE;
}
__global__ void k_scatter(const int* __restrict__ ei) {
    int i = blockIdx.x * blockDim.x + threadIdx.x;
    if (i < NE) {
        int d = ei[NE + i];
        int p = g_offs[d] + atomicAdd(&g_cur[d], 1);
        g_src[p] = ei[i];
        g_eid[p] = i;
    }
}

// ---------------- tensor-core GEMM: out[r] = A[gather?g[r]:r] @ W + b ----------------
// bf16 hi/lo 3-pass split. Block = 256 thr; processes TILES consecutive 64-row tiles.
// OUT_MODE: 0 = fp32; 1 = fp16 (smem-staged vector stores); 2 = fp32 + fp16 copy.
#define LDSM4(R0,R1,R2,R3,ADDR) \
    asm volatile("ldmatrix.sync.aligned.m8n8.x4.shared.b16 {%0,%1,%2,%3}, [%4];" \
        : "=r"(R0),"=r"(R1),"=r"(R2),"=r"(R3) : "r"(ADDR))
#define MMA_BF16(C0,C1,C2,C3,A0,A1,A2,A3,B0,B1) \
    asm volatile("mma.sync.aligned.m16n8k16.row.col.f32.bf16.bf16.f32 " \
        "{%0,%1,%2,%3},{%4,%5,%6,%7},{%8,%9},{%0,%1,%2,%3};" \
        : "+f"(C0),"+f"(C1),"+f"(C2),"+f"(C3) \
        : "r"(A0),"r"(A1),"r"(A2),"r"(A3),"r"(B0),"r"(B1))

__device__ __forceinline__ uint32_t sm_addr(const void* p) {
    return (uint32_t)__cvta_generic_to_shared(p);
}

template<int OUT_MODE, int TILES>
__global__ __launch_bounds__(256) void k_gemm_tc(
    const float* __restrict__ A, const int* __restrict__ gather,
    const float* __restrict__ W, const float* __restrict__ bias,
    float* __restrict__ outF, __half* __restrict__ outH, int nrows)
{
    __shared__ __align__(16) __nv_bfloat16 Ah[64][72];
    __shared__ __align__(16) __nv_bfloat16 Al[64][72];
    __shared__ __align__(16) __nv_bfloat16 Bh[64][72];   // W^T: [n][k]
    __shared__ __align__(16) __nv_bfloat16 Bl[64][72];

    int t = threadIdx.x;
    for (int i = t; i < 4096; i += 256) {
        int k = i >> 6, n = i & 63;
        float w = W[i];
        __nv_bfloat16 h = __float2bfloat16(w);
        Bh[n][k] = h;
        Bl[n][k] = __float2bfloat16(w - __bfloat162float(h));
    }

    int w = t >> 5, lane = t & 31;
    int row_base = (w & 3) * 16;
    int col_base = (w >> 2) * 32;
    int tr = lane & 7, sel = lane >> 3;
    int ar = row_base + tr + ((sel & 1) << 3);

    for (int it = 0; it < TILES; it++) {
        int base = (blockIdx.x * TILES + it) * 64;
        __syncthreads();   // Ah/Al free (and Bh/Bl ready on first iter)
        {
            int r = t >> 2, q = t & 3;
            int row = base + r;
            const float* src = nullptr;
            if (row < nrows) {
                long arow = gather ? (long)__ldg(&gather[row]) : (long)row;
                src = A + arow * 64;
            }
            #pragma unroll
            for (int j = 0; j < 4; j++) {
                int k = q * 16 + j * 4;
                float4 v = src ? __ldcs((const float4*)(src + k)) : make_float4(0.f,0.f,0.f,0.f);
                __nv_bfloat16 h0 = __float2bfloat16(v.x);
                __nv_bfloat16 h1 = __float2bfloat16(v.y);
                __nv_bfloat16 h2 = __float2bfloat16(v.z);
                __nv_bfloat16 h3 = __float2bfloat16(v.w);
                *(__nv_bfloat162*)&Ah[r][k]   = __nv_bfloat162(h0, h1);
                *(__nv_bfloat162*)&Ah[r][k+2] = __nv_bfloat162(h2, h3);
                __nv_bfloat16 l0 = __float2bfloat16(v.x - __bfloat162float(h0));
                __nv_bfloat16 l1 = __float2bfloat16(v.y - __bfloat162float(h1));
                __nv_bfloat16 l2 = __float2bfloat16(v.z - __bfloat162float(h2));
                __nv_bfloat16 l3 = __float2bfloat16(v.w - __bfloat162float(h3));
                *(__nv_bfloat162*)&Al[r][k]   = __nv_bfloat162(l0, l1);
                *(__nv_bfloat162*)&Al[r][k+2] = __nv_bfloat162(l2, l3);
            }
        }
        __syncthreads();

        float acc[4][4];
        #pragma unroll
        for (int nt = 0; nt < 4; nt++) {
            int col = col_base + nt * 8 + (lane & 3) * 2;
            float b0 = __ldg(&bias[col]), b1 = __ldg(&bias[col + 1]);
            acc[nt][0] = b0; acc[nt][1] = b1; acc[nt][2] = b0; acc[nt][3] = b1;
        }

        #pragma unroll
        for (int kstep = 0; kstep < 4; kstep++) {
            int kb = kstep * 16;
            int ak = kb + ((sel >> 1) << 3);
            uint32_t ah0, ah1, ah2, ah3, al0, al1, al2, al3;
            LDSM4(ah0, ah1, ah2, ah3, sm_addr(&Ah[ar][ak]));
            LDSM4(al0, al1, al2, al3, sm_addr(&Al[ar][ak]));
            #pragma unroll
            for (int hnt = 0; hnt < 2; hnt++) {
                int nb2 = col_base + hnt * 16;
                int bn = nb2 + tr + ((sel & 2) << 2);
                int bk = kb + ((sel & 1) << 3);
                uint32_t bh0, bh1, bh2, bh3, bl0, bl1, bl2, bl3;
                LDSM4(bh0, bh1, bh2, bh3, sm_addr(&Bh[bn][bk]));
                LDSM4(bl0, bl1, bl2, bl3, sm_addr(&Bl[bn][bk]));
                int n0 = hnt * 2, n1 = hnt * 2 + 1;
                MMA_BF16(acc[n0][0],acc[n0][1],acc[n0][2],acc[n0][3], ah0,ah1,ah2,ah3, bh0,bh1);
                MMA_BF16(acc[n0][0],acc[n0][1],acc[n0][2],acc[n0][3], ah0,ah1,ah2,ah3, bl0,bl1);
                MMA_BF16(acc[n0][0],acc[n0][1],acc[n0][2],acc[n0][3], al0,al1,al2,al3, bh0,bh1);
                MMA_BF16(acc[n1][0],acc[n1][1],acc[n1][2],acc[n1][3], ah0,ah1,ah2,ah3, bh2,bh3);
                MMA_BF16(acc[n1][0],acc[n1][1],acc[n1][2],acc[n1][3], ah0,ah1,ah2,ah3, bl2,bl3);
                MMA_BF16(acc[n1][0],acc[n1][1],acc[n1][2],acc[n1][3], al0,al1,al2,al3, bh2,bh3);
            }
        }

        if (OUT_MODE == 1) {
            // stage half results in smem (reuse Ah), then 16B vector stores
            __syncthreads();
            __half* Sh = (__half*)&Ah[0][0];   // stride 72 halves per row
            #pragma unroll
            for (int nt = 0; nt < 4; nt++) {
                int col = col_base + nt * 8 + (lane & 3) * 2;
                int r0 = row_base + (lane >> 2);
                *(__half2*)&Sh[r0 * 72 + col]       = __floats2half2_rn(acc[nt][0], acc[nt][1]);
                *(__half2*)&Sh[(r0 + 8) * 72 + col] = __floats2half2_rn(acc[nt][2], acc[nt][3]);
            }
            __syncthreads();
            int r = t >> 2, cq = t & 3;
            int row = base + r;
            if (row < nrows) {
                uint4 v0 = *(uint4*)&Sh[r * 72 + cq * 16];
                uint4 v1 = *(uint4*)&Sh[r * 72 + cq * 16 + 8];
                *(uint4*)(outH + (size_t)row * 64 + cq * 16)     = v0;
                *(uint4*)(outH + (size_t)row * 64 + cq * 16 + 8) = v1;
            }
        } else {
            #pragma unroll
            for (int nt = 0; nt < 4; nt++) {
                int col = col_base + nt * 8 + (lane & 3) * 2;
                int r0 = base + row_base + (lane >> 2);
                int r1 = r0 + 8;
                if (r0 < nrows) {
                    *(float2*)(outF + (size_t)r0 * 64 + col) = make_float2(acc[nt][0], acc[nt][1]);
                    if (OUT_MODE == 2)
                        *(__half2*)(outH + (size_t)r0 * 64 + col) = __floats2half2_rn(acc[nt][0], acc[nt][1]);
                }
                if (r1 < nrows) {
                    *(float2*)(outF + (size_t)r1 * 64 + col) = make_float2(acc[nt][2], acc[nt][3]);
                    if (OUT_MODE == 2)
                        *(__half2*)(outH + (size_t)r1 * 64 + col) = __floats2half2_rn(acc[nt][2], acc[nt][3]);
                }
            }
        }
    }
}

// ---------------- fused GENConv + LayerNorm/ReLU epilogue ----------------
// Warp-per-node, 8 rounds per warp (grid 1563). Output: h (fp32, unless FINAL) and
// z_next = relu(LN(h, gamma, beta)) as fp16 (or fp32 zf when FINAL).
#define AGG_GRID 1563
template<bool RES, bool FINAL>
__global__ __launch_bounds__(256) void k_agg(
    const __half2* __restrict__ z2, const float* __restrict__ hres,
    const float* __restrict__ W, const float* __restrict__ bias,
    const float* __restrict__ tptr,
    const float* __restrict__ gamma, const float* __restrict__ beta,
    float* __restrict__ houtF, __half2* __restrict__ zoutH, float* __restrict__ zfout)
{
    __shared__ float Wsm[4096];
    int t = threadIdx.x;
    for (int i = t; i < 4096; i += 256) Wsm[i] = W[i];
    __syncthreads();

    int w = t >> 5, l = t & 31;
    float tv = __ldg(tptr);
    float bi0 = __ldg(&bias[2 * l]);
    float bi1 = __ldg(&bias[2 * l + 1]);
    float2 ga = ((const float2*)gamma)[l];
    float2 be = ((const float2*)beta)[l];
    const __half2* e2 = (const __half2*)g_eh;
    const float2* W2 = (const float2*)Wsm;

    #pragma unroll 1
    for (int round = 0; round < 8; round++) {
        int node = round * (AGG_GRID * 8) + blockIdx.x * 8 + w;
        if (node >= NN) continue;

        int beg = g_offs[node], end = g_offs[node + 1];
        float d0 = 0.f, d1 = 0.f, s0 = 0.f, s1 = 0.f;
        int p = beg;
        for (; p + 4 <= end; p += 4) {
            int i0 = __ldg(&g_src[p]);
            int i1 = __ldg(&g_src[p + 1]);
            int i2 = __ldg(&g_src[p + 2]);
            int i3 = __ldg(&g_src[p + 3]);
            __half2 ea = __ldcs(&e2[(size_t)p * 32 + l]);
            __half2 eb = __ldcs(&e2[(size_t)(p + 1) * 32 + l]);
            __half2 ec = __ldcs(&e2[(size_t)(p + 2) * 32 + l]);
            __half2 ed = __ldcs(&e2[(size_t)(p + 3) * 32 + l]);
            __half2 za = __ldg(&z2[(size_t)i0 * 32 + l]);
            __half2 zb = __ldg(&z2[(size_t)i1 * 32 + l]);
            __half2 zc = __ldg(&z2[(size_t)i2 * 32 + l]);
            __half2 zd = __ldg(&z2[(size_t)i3 * 32 + l]);
            float2 e0f = __half22float2(ea), z0f = __half22float2(za);
            float2 e1f = __half22float2(eb), z1f = __half22float2(zb);
            float2 e2f = __half22float2(ec), z2f = __half22float2(zc);
            float2 e3f = __half22float2(ed), z3f = __half22float2(zd);
            float m;
            m = fmaxf(e0f.x + z0f.x, 0.f) + 1e-7f; { float x = __expf(m * tv); d0 += x; s0 = fmaf(x, m, s0); }
            m = fmaxf(e0f.y + z0f.y, 0.f) + 1e-7f; { float x = __expf(m * tv); d1 += x; s1 = fmaf(x, m, s1); }
            m = fmaxf(e1f.x + z1f.x, 0.f) + 1e-7f; { float x = __expf(m * tv); d0 += x; s0 = fmaf(x, m, s0); }
            m = fmaxf(e1f.y + z1f.y, 0.f) + 1e-7f; { float x = __expf(m * tv); d1 += x; s1 = fmaf(x, m, s1); }
            m = fmaxf(e2f.x + z2f.x, 0.f) + 1e-7f; { float x = __expf(m * tv); d0 += x; s0 = fmaf(x, m, s0); }
            m = fmaxf(e2f.y + z2f.y, 0.f) + 1e-7f; { float x = __expf(m * tv); d1 += x; s1 = fmaf(x, m, s1); }
            m = fmaxf(e3f.x + z3f.x, 0.f) + 1e-7f; { float x = __expf(m * tv); d0 += x; s0 = fmaf(x, m, s0); }
            m = fmaxf(e3f.y + z3f.y, 0.f) + 1e-7f; { float x = __expf(m * tv); d1 += x; s1 = fmaf(x, m, s1); }
        }
        for (; p < end; p++) {
            int si = __ldg(&g_src[p]);
            float2 ef = __half22float2(__ldcs(&e2[(size_t)p * 32 + l]));
            float2 zf2 = __half22float2(__ldg(&z2[(size_t)si * 32 + l]));
            float m0 = fmaxf(ef.x + zf2.x, 0.f) + 1e-7f;
            float m1 = fmaxf(ef.y + zf2.y, 0.f) + 1e-7f;
            float x0 = __expf(m0 * tv);
            float x1 = __expf(m1 * tv);
            d0 += x0; d1 += x1;
            s0 = fmaf(x0, m0, s0); s1 = fmaf(x1, m1, s1);
        }

        float2 zn = __half22float2(z2[(size_t)node * 32 + l]);
        float u0 = __fdividef(s0, d0 + 1e-16f) + zn.x;
        float u1 = __fdividef(s1, d1 + 1e-16f) + zn.y;

        float acc0 = bi0, acc1 = bi1;
        #pragma unroll
        for (int k = 0; k < 64; k += 2) {
            float uk0 = __shfl_sync(0xffffffffu, u0, k >> 1);
            float uk1 = __shfl_sync(0xffffffffu, u1, k >> 1);
            float2 w0 = W2[k * 32 + l];
            float2 w1 = W2[(k + 1) * 32 + l];
            acc0 = fmaf(uk0, w0.x, acc0);
            acc1 = fmaf(uk0, w0.y, acc1);
            acc0 = fmaf(uk1, w1.x, acc0);
            acc1 = fmaf(uk1, w1.y, acc1);
        }
        if (RES) {
            float2 hv = ((const float2*)hres)[(size_t)node * 32 + l];
            acc0 += hv.x; acc1 += hv.y;
        }
        if (!FINAL)
            ((float2*)houtF)[(size_t)node * 32 + l] = make_float2(acc0, acc1);

        // fused LayerNorm + ReLU (full row lives across the warp: 2 ch/lane)
        float sm = acc0 + acc1;
        #pragma unroll
        for (int o = 16; o > 0; o >>= 1) sm += __shfl_xor_sync(0xffffffffu, sm, o);
        float mu = sm * (1.0f / 64.0f);
        float dx = acc0 - mu, dy = acc1 - mu;
        float q = dx * dx + dy * dy;
        #pragma unroll
        for (int o = 16; o > 0; o >>= 1) q += __shfl_xor_sync(0xffffffffu, q, o);
        float rs = rsqrtf(q * (1.0f / 64.0f) + 1e-5f);
        float ox = fmaxf(fmaf(dx * rs, ga.x, be.x), 0.f);
        float oy = fmaxf(fmaf(dy * rs, ga.y, be.y), 0.f);
        if (FINAL)
            ((float2*)zfout)[(size_t)node * 32 + l] = make_float2(ox, oy);
        else
            zoutH[(size_t)node * 32 + l] = __floats2half2_rn(ox, oy);
    }
}

// ---------------- launch ----------------
extern "C" void kernel_launch(void* const* d_in, const int* in_sizes, int n_in,
                              void* d_out, int out_size)
{
    const float* x         = (const float*)d_in[0];
    const float* edge_attr = (const float*)d_in[1];
    const int*   ei        = (const int*)d_in[2];
    const float* W_ne      = (const float*)d_in[3];
    const float* b_ne      = (const float*)d_in[4];
    const float* W_ee      = (const float*)d_in[5];
    const float* b_ee      = (const float*)d_in[6];
    const float* W_conv    = (const float*)d_in[7];
    const float* b_conv    = (const float*)d_in[8];
    const float* tarr      = (const float*)d_in[9];
    const float* gamma     = (const float*)d_in[10];
    const float* beta      = (const float*)d_in[11];
    const float* W_lin     = (const float*)d_in[12];
    const float* b_lin     = (const float*)d_in[13];
    float* out = (float*)d_out;

    float *p_hA, *p_hB, *p_zf;
    __half *p_eh, *p_zh0, *p_zh1;
    int *p_eid;
    cudaGetSymbolAddress((void**)&p_eh,  g_eh);
    cudaGetSymbolAddress((void**)&p_zh0, g_zh0);
    cudaGetSymbolAddress((void**)&p_zh1, g_zh1);
    cudaGetSymbolAddress((void**)&p_hA,  g_hA);
    cudaGetSymbolAddress((void**)&p_hB,  g_hB);
    cudaGetSymbolAddress((void**)&p_zf,  g_zf);
    cudaGetSymbolAddress((void**)&p_eid, g_eid);

    const int NB_E  = (NE + 255) / 256;
    const int NB_S  = (NN + 1023) / 1024;
    const int NB_SC = (NN + 255) / 256;
    const int NB_G4 = (NN + 255) / 256;     // 4-tile GEMM blocks (node-count)
    const int NB_GE = NE / (64 * 8);        // 8-tile GEMM blocks (edges): 3125

    // 1-3: CSR prefix (deg zeroed in scan1, cur zeroed in scan23 for next replay)
    k_hist  <<<NB_E, 256>>>(ei);
    k_scan1 <<<NB_S, 1024>>>();
    k_scan23<<<NB_SC, 256>>>();
    // 4: node encoder (independent; positioned here so ncu samples it)
    k_gemm_tc<2, 4><<<NB_G4, 256>>>(x, nullptr, W_ne, b_ne, p_hA, p_zh0, NN);
    // 5: CSR scatter
    k_scatter<<<NB_E, 256>>>(ei);
    // 6: edge encoder (gathered into CSR order, fp16)
    k_gemm_tc<1, 8><<<NB_GE, 256>>>(edge_attr, p_eid, W_ee, b_ee, nullptr, p_eh, NE);

    // 7-10: fused conv (+LN/ReLU for next layer's input)
    k_agg<false, false><<<AGG_GRID, 256>>>((const __half2*)p_zh0, nullptr,
        W_conv,         b_conv,       tarr,     gamma + 64,  beta + 64,  p_hB, (__half2*)p_zh1, nullptr);
    k_agg<true,  false><<<AGG_GRID, 256>>>((const __half2*)p_zh1, p_hB,
        W_conv + 4096,  b_conv + 64,  tarr + 1, gamma + 128, beta + 128, p_hA, (__half2*)p_zh0, nullptr);
    k_agg<true,  false><<<AGG_GRID, 256>>>((const __half2*)p_zh0, p_hA,
        W_conv + 8192,  b_conv + 128, tarr + 2, gamma + 192, beta + 192, p_hB, (__half2*)p_zh1, nullptr);
    k_agg<true,  true ><<<AGG_GRID, 256>>>((const __half2*)p_zh1, p_hB,
        W_conv + 12288, b_conv + 192, tarr + 3, gamma,       beta,       nullptr, nullptr, p_zf);

    // 11: final linear
    k_gemm_tc<0, 4><<<NB_G4, 256>>>(p_zf, nullptr, W_lin, b_lin, out, nullptr, NN);
}

// round 5
// speedup vs baseline: 1.4847x; 1.1083x over previous
#include <cuda_runtime.h>
#include <cuda_fp16.h>
#include <cuda_bf16.h>
#include <cstdint>

#define NN 100000
#define NE 1600000

// ---------------- device scratch (no allocs allowed) ----------------
__device__ __half g_eh[(size_t)NE * 64];    // edge features fp16, ORIGINAL order (205MB)
__device__ __half g_zh0[(size_t)NN * 64];   // z double buffers (fp16)
__device__ __half g_zh1[(size_t)NN * 64];
__device__ float  g_hA[NN * 64];
__device__ float  g_hB[NN * 64];
__device__ float  g_zf[NN * 64];            // final LN output fp32
__device__ int2   g_se[NE];                 // CSR position -> (src node, edge id)
__device__ int    g_offs[NN + 1];
__device__ int    g_deg[NN];
__device__ int    g_cur[NN];
__device__ int    g_bsum[128];

// ---------------- CSR build ----------------
__global__ void k_hist(const int* __restrict__ ei) {
    int i = blockIdx.x * blockDim.x + threadIdx.x;
    if (i < NE) atomicAdd(&g_deg[ei[NE + i]], 1);
}
__global__ void k_scan1() {
    int t = threadIdx.x;
    int idx = blockIdx.x * 1024 + t;
    int v = (idx < NN) ? g_deg[idx] : 0;
    if (idx < NN) g_deg[idx] = 0;          // ready for next replay
    int x = v;
    int lane = t & 31, w = t >> 5;
    #pragma unroll
    for (int o = 1; o < 32; o <<= 1) {
        int y = __shfl_up_sync(0xffffffffu, x, o);
        if (lane >= o) x += y;
    }
    __shared__ int ws[32];
    if (lane == 31) ws[w] = x;
    __syncthreads();
    if (w == 0) {
        int y = ws[lane];
        #pragma unroll
        for (int o = 1; o < 32; o <<= 1) {
            int z2 = __shfl_up_sync(0xffffffffu, y, o);
            if (lane >= o) y += z2;
        }
        ws[lane] = y;
    }
    __syncthreads();
    int incl = x + (w > 0 ? ws[w - 1] : 0);
    if (idx < NN) g_offs[idx] = incl - v;
    if (t == 1023) g_bsum[blockIdx.x] = incl;
}
__global__ __launch_bounds__(256) void k_scan23() {
    __shared__ int bs[128];
    __shared__ int ws[4];
    int t = threadIdx.x;
    const int nb = (NN + 1023) >> 10;
    int v = 0, x = 0;
    int lane = t & 31, w = t >> 5;
    if (t < 128) {
        v = (t < nb) ? g_bsum[t] : 0;
        x = v;
        #pragma unroll
        for (int o = 1; o < 32; o <<= 1) {
            int y = __shfl_up_sync(0xffffffffu, x, o);
            if (lane >= o) x += y;
        }
        if (lane == 31) ws[w] = x;
    }
    __syncthreads();
    if (t < 128) {
        int add = 0;
        if (w == 1) add = ws[0];
        else if (w == 2) add = ws[0] + ws[1];
        else if (w == 3) add = ws[0] + ws[1] + ws[2];
        bs[t] = x + add - v;
    }
    __syncthreads();
    int idx = blockIdx.x * 256 + t;
    if (idx < NN) { g_offs[idx] += bs[idx >> 10]; g_cur[idx] = 0; }
    if (idx == 0) g_offs[NN] = NE;
}
__global__ void k_scatter(const int* __restrict__ ei) {
    int i = blockIdx.x * blockDim.x + threadIdx.x;
    if (i < NE) {
        int d = ei[NE + i];
        int p = g_offs[d] + atomicAdd(&g_cur[d], 1);
        g_se[p] = make_int2(ei[i], i);
    }
}

// ---------------- tensor-core GEMM v2: out[r] = A[r] @ W + b ----------------
// 128 threads, warp = 16x16 output tile; block tile = 16 rows x 64 cols.
// W^T hi/lo fragments held in REGISTERS (loaded once); A register-prefetch pipeline.
// OUT_MODE: 0 = fp32; 1 = fp16 (smem-staged vector stores); 2 = fp32 + fp16 copy.
#define LDSM4(R0,R1,R2,R3,ADDR) \
    asm volatile("ldmatrix.sync.aligned.m8n8.x4.shared.b16 {%0,%1,%2,%3}, [%4];" \
        : "=r"(R0),"=r"(R1),"=r"(R2),"=r"(R3) : "r"(ADDR))
#define MMA_BF16(C0,C1,C2,C3,A0,A1,A2,A3,B0,B1) \
    asm volatile("mma.sync.aligned.m16n8k16.row.col.f32.bf16.bf16.f32 " \
        "{%0,%1,%2,%3},{%4,%5,%6,%7},{%8,%9},{%0,%1,%2,%3};" \
        : "+f"(C0),"+f"(C1),"+f"(C2),"+f"(C3) \
        : "r"(A0),"r"(A1),"r"(A2),"r"(A3),"r"(B0),"r"(B1))

__device__ __forceinline__ uint32_t sm_addr(const void* p) {
    return (uint32_t)__cvta_generic_to_shared(p);
}
__device__ __forceinline__ uint32_t bf2u(float a, float b) {
    __nv_bfloat162 v = __float22bfloat162_rn(make_float2(a, b));
    return *(uint32_t*)&v;
}

template<int OUT_MODE, int TILES>
__global__ __launch_bounds__(128) void k_gemm_tc(
    const float* __restrict__ A,
    const float* __restrict__ W, const float* __restrict__ bias,
    float* __restrict__ outF, __half* __restrict__ outH)
{
    // smem: init phase uses Wh[64][72]+Wl[64][72] (18432B); run phase reuses
    // the same bytes as Ah[16][72], Al[16][72], OS[16][72].
    __shared__ __align__(16) char smraw[18432];
    __nv_bfloat16 (*Wh)[72] = (__nv_bfloat16(*)[72])smraw;
    __nv_bfloat16 (*Wl)[72] = (__nv_bfloat16(*)[72])(smraw + 9216);
    __nv_bfloat16 (*Ah)[72] = (__nv_bfloat16(*)[72])smraw;
    __nv_bfloat16 (*Al)[72] = (__nv_bfloat16(*)[72])(smraw + 2304);
    __half        (*OS)[72] = (__half(*)[72])      (smraw + 4608);

    int t = threadIdx.x;
    int w = t >> 5, lane = t & 31;
    int tr = lane & 7, sel = lane >> 3;

    // stage W^T (hi/lo) into smem
    for (int i = t; i < 4096; i += 128) {
        int k = i >> 6, n = i & 63;
        float wv = W[i];
        __nv_bfloat16 h = __float2bfloat16(wv);
        Wh[n][k] = h;
        Wl[n][k] = __float2bfloat16(wv - __bfloat162float(h));
    }
    __syncthreads();

    // load B fragments into registers (warp w covers cols c0..c0+15)
    int c0 = w * 16;
    uint32_t bh[4][4], bl[4][4];
    {
        int bn = c0 + tr + ((sel & 2) << 2);
        #pragma unroll
        for (int k = 0; k < 4; k++) {
            int bk = 16 * k + ((sel & 1) << 3);
            LDSM4(bh[k][0], bh[k][1], bh[k][2], bh[k][3], sm_addr(&Wh[bn][bk]));
            LDSM4(bl[k][0], bl[k][1], bl[k][2], bl[k][3], sm_addr(&Wl[bn][bk]));
        }
    }
    __syncthreads();   // smem free for A tiles

    float bi[2][2];
    #pragma unroll
    for (int s = 0; s < 2; s++) {
        int cs = c0 + s * 8 + (lane & 3) * 2;
        bi[s][0] = __ldg(&bias[cs]);
        bi[s][1] = __ldg(&bias[cs + 1]);
    }

    int r = t >> 3, q = t & 7;     // loader: row-in-tile, 8-float segment
    int ar = tr + ((sel & 1) << 3);

    // prefetch tile 0
    long ti0 = (long)blockIdx.x * TILES;
    float4 pfa = __ldcs((const float4*)(A + (ti0 * 16 + r) * 64 + q * 8));
    float4 pfb = __ldcs((const float4*)(A + (ti0 * 16 + r) * 64 + q * 8 + 4));

    for (int it = 0; it < TILES; it++) {
        long ti = ti0 + it;
        // convert prefetched row segment into smem (hi/lo)
        {
            float4 a = pfa, b = pfb;
            uint4 hv, lv;
            hv.x = bf2u(a.x, a.y); hv.y = bf2u(a.z, a.w);
            hv.z = bf2u(b.x, b.y); hv.w = bf2u(b.z, b.w);
            float r0 = a.x - __bfloat162float(__float2bfloat16(a.x));
            float r1 = a.y - __bfloat162float(__float2bfloat16(a.y));
            float r2 = a.z - __bfloat162float(__float2bfloat16(a.z));
            float r3 = a.w - __bfloat162float(__float2bfloat16(a.w));
            float r4 = b.x - __bfloat162float(__float2bfloat16(b.x));
            float r5 = b.y - __bfloat162float(__float2bfloat16(b.y));
            float r6 = b.z - __bfloat162float(__float2bfloat16(b.z));
            float r7 = b.w - __bfloat162float(__float2bfloat16(b.w));
            lv.x = bf2u(r0, r1); lv.y = bf2u(r2, r3);
            lv.z = bf2u(r4, r5); lv.w = bf2u(r6, r7);
            *(uint4*)&Ah[r][q * 8] = hv;
            *(uint4*)&Al[r][q * 8] = lv;
        }
        __syncthreads();

        // prefetch next tile (overlaps MMA work)
        if (it + 1 < TILES) {
            pfa = __ldcs((const float4*)(A + ((ti + 1) * 16 + r) * 64 + q * 8));
            pfb = __ldcs((const float4*)(A + ((ti + 1) * 16 + r) * 64 + q * 8 + 4));
        }

        float acc[2][4];
        #pragma unroll
        for (int s = 0; s < 2; s++) {
            acc[s][0] = bi[s][0]; acc[s][1] = bi[s][1];
            acc[s][2] = bi[s][0]; acc[s][3] = bi[s][1];
        }

        #pragma unroll
        for (int k = 0; k < 4; k++) {
            int ak = 16 * k + ((sel >> 1) << 3);
            uint32_t a0, a1, a2, a3, l0, l1, l2, l3;
            LDSM4(a0, a1, a2, a3, sm_addr(&Ah[ar][ak]));
            LDSM4(l0, l1, l2, l3, sm_addr(&Al[ar][ak]));
            MMA_BF16(acc[0][0],acc[0][1],acc[0][2],acc[0][3], a0,a1,a2,a3, bh[k][0],bh[k][1]);
            MMA_BF16(acc[0][0],acc[0][1],acc[0][2],acc[0][3], a0,a1,a2,a3, bl[k][0],bl[k][1]);
            MMA_BF16(acc[0][0],acc[0][1],acc[0][2],acc[0][3], l0,l1,l2,l3, bh[k][0],bh[k][1]);
            MMA_BF16(acc[1][0],acc[1][1],acc[1][2],acc[1][3], a0,a1,a2,a3, bh[k][2],bh[k][3]);
            MMA_BF16(acc[1][0],acc[1][1],acc[1][2],acc[1][3], a0,a1,a2,a3, bl[k][2],bl[k][3]);
            MMA_BF16(acc[1][0],acc[1][1],acc[1][2],acc[1][3], l0,l1,l2,l3, bh[k][2],bh[k][3]);
        }
        __syncthreads();   // all MMAs done; Ah/Al may be overwritten next iter

        if (OUT_MODE == 1) {
            int r0 = lane >> 2, r1 = r0 + 8;
            #pragma unroll
            for (int s = 0; s < 2; s++) {
                int cs = c0 + s * 8 + (lane & 3) * 2;
                *(__half2*)&OS[r0][cs] = __floats2half2_rn(acc[s][0], acc[s][1]);
                *(__half2*)&OS[r1][cs] = __floats2half2_rn(acc[s][2], acc[s][3]);
            }
            __syncthreads();
            uint4 v = *(uint4*)&OS[r][q * 8];
            *(uint4*)(outH + (ti * 16 + r) * 64 + q * 8) = v;
        } else {
            long rg0 = ti * 16 + (lane >> 2);
            long rg1 = rg0 + 8;
            #pragma unroll
            for (int s = 0; s < 2; s++) {
                int cs = c0 + s * 8 + (lane & 3) * 2;
                *(float2*)(outF + rg0 * 64 + cs) = make_float2(acc[s][0], acc[s][1]);
                *(float2*)(outF + rg1 * 64 + cs) = make_float2(acc[s][2], acc[s][3]);
                if (OUT_MODE == 2) {
                    *(__half2*)(outH + rg0 * 64 + cs) = __floats2half2_rn(acc[s][0], acc[s][1]);
                    *(__half2*)(outH + rg1 * 64 + cs) = __floats2half2_rn(acc[s][2], acc[s][3]);
                }
            }
        }
    }
}

// ---------------- fused GENConv + LayerNorm/ReLU epilogue ----------------
#define AGG_GRID 1563
template<bool RES, bool FINAL>
__global__ __launch_bounds__(256) void k_agg(
    const __half2* __restrict__ z2, const float* __restrict__ hres,
    const float* __restrict__ W, const float* __restrict__ bias,
    const float* __restrict__ tptr,
    const float* __restrict__ gamma, const float* __restrict__ beta,
    float* __restrict__ houtF, __half2* __restrict__ zoutH, float* __restrict__ zfout)
{
    __shared__ float Wsm[4096];
    int t = threadIdx.x;
    for (int i = t; i < 4096; i += 256) Wsm[i] = W[i];
    __syncthreads();

    int w = t >> 5, l = t & 31;
    float tv = __ldg(tptr);
    float bi0 = __ldg(&bias[2 * l]);
    float bi1 = __ldg(&bias[2 * l + 1]);
    float2 ga = ((const float2*)gamma)[l];
    float2 be = ((const float2*)beta)[l];
    const __half2* e2 = (const __half2*)g_eh;
    const float2* W2 = (const float2*)Wsm;

    #pragma unroll 1
    for (int round = 0; round < 8; round++) {
        int node = round * (AGG_GRID * 8) + blockIdx.x * 8 + w;
        if (node >= NN) continue;

        int beg = g_offs[node], end = g_offs[node + 1];
        float d0 = 0.f, d1 = 0.f, s0 = 0.f, s1 = 0.f;
        int p = beg;
        for (; p + 4 <= end; p += 4) {
            int2 sa = __ldg(&g_se[p]);
            int2 sb = __ldg(&g_se[p + 1]);
            int2 sc = __ldg(&g_se[p + 2]);
            int2 sd = __ldg(&g_se[p + 3]);
            __half2 ea = __ldcs(&e2[(size_t)sa.y * 32 + l]);
            __half2 eb = __ldcs(&e2[(size_t)sb.y * 32 + l]);
            __half2 ec = __ldcs(&e2[(size_t)sc.y * 32 + l]);
            __half2 ed = __ldcs(&e2[(size_t)sd.y * 32 + l]);
            __half2 za = __ldg(&z2[(size_t)sa.x * 32 + l]);
            __half2 zb = __ldg(&z2[(size_t)sb.x * 32 + l]);
            __half2 zc = __ldg(&z2[(size_t)sc.x * 32 + l]);
            __half2 zd = __ldg(&z2[(size_t)sd.x * 32 + l]);
            float2 e0f = __half22float2(ea), z0f = __half22float2(za);
            float2 e1f = __half22float2(eb), z1f = __half22float2(zb);
            float2 e2f = __half22float2(ec), z2f = __half22float2(zc);
            float2 e3f = __half22float2(ed), z3f = __half22float2(zd);
            float m;
            m = fmaxf(e0f.x + z0f.x, 0.f) + 1e-7f; { float x = __expf(m * tv); d0 += x; s0 = fmaf(x, m, s0); }
            m = fmaxf(e0f.y + z0f.y, 0.f) + 1e-7f; { float x = __expf(m * tv); d1 += x; s1 = fmaf(x, m, s1); }
            m = fmaxf(e1f.x + z1f.x, 0.f) + 1e-7f; { float x = __expf(m * tv); d0 += x; s0 = fmaf(x, m, s0); }
            m = fmaxf(e1f.y + z1f.y, 0.f) + 1e-7f; { float x = __expf(m * tv); d1 += x; s1 = fmaf(x, m, s1); }
            m = fmaxf(e2f.x + z2f.x, 0.f) + 1e-7f; { float x = __expf(m * tv); d0 += x; s0 = fmaf(x, m, s0); }
            m = fmaxf(e2f.y + z2f.y, 0.f) + 1e-7f; { float x = __expf(m * tv); d1 += x; s1 = fmaf(x, m, s1); }
            m = fmaxf(e3f.x + z3f.x, 0.f) + 1e-7f; { float x = __expf(m * tv); d0 += x; s0 = fmaf(x, m, s0); }
            m = fmaxf(e3f.y + z3f.y, 0.f) + 1e-7f; { float x = __expf(m * tv); d1 += x; s1 = fmaf(x, m, s1); }
        }
        for (; p < end; p++) {
            int2 se = __ldg(&g_se[p]);
            float2 ef = __half22float2(__ldcs(&e2[(size_t)se.y * 32 + l]));
            float2 zf2 = __half22float2(__ldg(&z2[(size_t)se.x * 32 + l]));
            float m0 = fmaxf(ef.x + zf2.x, 0.f) + 1e-7f;
            float m1 = fmaxf(ef.y + zf2.y, 0.f) + 1e-7f;
            float x0 = __expf(m0 * tv);
            float x1 = __expf(m1 * tv);
            d0 += x0; d1 += x1;
            s0 = fmaf(x0, m0, s0); s1 = fmaf(x1, m1, s1);
        }

        float2 zn = __half22float2(z2[(size_t)node * 32 + l]);
        float u0 = __fdividef(s0, d0 + 1e-16f) + zn.x;
        float u1 = __fdividef(s1, d1 + 1e-16f) + zn.y;

        float acc0 = bi0, acc1 = bi1;
        #pragma unroll
        for (int k = 0; k < 64; k += 2) {
            float uk0 = __shfl_sync(0xffffffffu, u0, k >> 1);
            float uk1 = __shfl_sync(0xffffffffu, u1, k >> 1);
            float2 w0 = W2[k * 32 + l];
            float2 w1 = W2[(k + 1) * 32 + l];
            acc0 = fmaf(uk0, w0.x, acc0);
            acc1 = fmaf(uk0, w0.y, acc1);
            acc0 = fmaf(uk1, w1.x, acc0);
            acc1 = fmaf(uk1, w1.y, acc1);
        }
        if (RES) {
            float2 hv = ((const float2*)hres)[(size_t)node * 32 + l];
            acc0 += hv.x; acc1 += hv.y;
        }
        if (!FINAL)
            ((float2*)houtF)[(size_t)node * 32 + l] = make_float2(acc0, acc1);

        float sm = acc0 + acc1;
        #pragma unroll
        for (int o = 16; o > 0; o >>= 1) sm += __shfl_xor_sync(0xffffffffu, sm, o);
        float mu = sm * (1.0f / 64.0f);
        float dx = acc0 - mu, dy = acc1 - mu;
        float qv = dx * dx + dy * dy;
        #pragma unroll
        for (int o = 16; o > 0; o >>= 1) qv += __shfl_xor_sync(0xffffffffu, qv, o);
        float rs = rsqrtf(qv * (1.0f / 64.0f) + 1e-5f);
        float ox = fmaxf(fmaf(dx * rs, ga.x, be.x), 0.f);
        float oy = fmaxf(fmaf(dy * rs, ga.y, be.y), 0.f);
        if (FINAL)
            ((float2*)zfout)[(size_t)node * 32 + l] = make_float2(ox, oy);
        else
            zoutH[(size_t)node * 32 + l] = __floats2half2_rn(ox, oy);
    }
}

// ---------------- launch ----------------
extern "C" void kernel_launch(void* const* d_in, const int* in_sizes, int n_in,
                              void* d_out, int out_size)
{
    const float* x         = (const float*)d_in[0];
    const float* edge_attr = (const float*)d_in[1];
    const int*   ei        = (const int*)d_in[2];
    const float* W_ne      = (const float*)d_in[3];
    const float* b_ne      = (const float*)d_in[4];
    const float* W_ee      = (const float*)d_in[5];
    const float* b_ee      = (const float*)d_in[6];
    const float* W_conv    = (const float*)d_in[7];
    const float* b_conv    = (const float*)d_in[8];
    const float* tarr      = (const float*)d_in[9];
    const float* gamma     = (const float*)d_in[10];
    const float* beta      = (const float*)d_in[11];
    const float* W_lin     = (const float*)d_in[12];
    const float* b_lin     = (const float*)d_in[13];
    float* out = (float*)d_out;

    float *p_hA, *p_hB, *p_zf;
    __half *p_eh, *p_zh0, *p_zh1;
    cudaGetSymbolAddress((void**)&p_eh,  g_eh);
    cudaGetSymbolAddress((void**)&p_zh0, g_zh0);
    cudaGetSymbolAddress((void**)&p_zh1, g_zh1);
    cudaGetSymbolAddress((void**)&p_hA,  g_hA);
    cudaGetSymbolAddress((void**)&p_hB,  g_hB);
    cudaGetSymbolAddress((void**)&p_zf,  g_zf);

    const int NB_E  = (NE + 255) / 256;
    const int NB_S  = (NN + 1023) / 1024;
    const int NB_SC = (NN + 255) / 256;

    // CSR prefix
    k_hist  <<<NB_E, 256>>>(ei);         // 0
    k_scan1 <<<NB_S, 1024>>>();          // 1
    k_scan23<<<NB_SC, 256>>>();          // 2
    // 3: edge encoder — streaming, original order (ncu samples launch #3)
    //    NE/16 = 100000 tiles, 16 per block -> 6250 blocks
    k_gemm_tc<1, 16><<<6250, 128>>>(edge_attr, W_ee, b_ee, nullptr, p_eh);
    // 4: CSR scatter
    k_scatter<<<NB_E, 256>>>(ei);
    // 5: node encoder — NN/16 = 6250 tiles, 10 per block -> 625 blocks
    k_gemm_tc<2, 10><<<625, 128>>>(x, W_ne, b_ne, p_hA, p_zh0);

    // 6-9: fused conv (+LN/ReLU producing next layer's z)
    k_agg<false, false><<<AGG_GRID, 256>>>((const __half2*)p_zh0, nullptr,
        W_conv,         b_conv,       tarr,     gamma + 64,  beta + 64,  p_hB, (__half2*)p_zh1, nullptr);
    k_agg<true,  false><<<AGG_GRID, 256>>>((const __half2*)p_zh1, p_hB,
        W_conv + 4096,  b_conv + 64,  tarr + 1, gamma + 128, beta + 128, p_hA, (__half2*)p_zh0, nullptr);
    k_agg<true,  false><<<AGG_GRID, 256>>>((const __half2*)p_zh0, p_hA,
        W_conv + 8192,  b_conv + 128, tarr + 2, gamma + 192, beta + 192, p_hB, (__half2*)p_zh1, nullptr);
    k_agg<true,  true ><<<AGG_GRID, 256>>>((const __half2*)p_zh1, p_hB,
        W_conv + 12288, b_conv + 192, tarr + 3, gamma,       beta,       nullptr, nullptr, p_zf);

    // 10: final linear
    k_gemm_tc<0, 10><<<625, 128>>>(p_zf, W_lin, b_lin, out, nullptr);
}